// round 13
// baseline (speedup 1.0000x reference)
#include <cuda_runtime.h>
#include <cuda_fp16.h>
#include <cstdint>

#define NMAX 50000
#define EMAX 800000
#define FDIM 96
#define DEG_PAD 128
#define HROW 48   // half2 per row
#define QROW 48   // uint32 (2x int16) per row
#define QSCALE 4096.0f
#define QINV (1.0f / 4096.0f)

// ---------------- scratch (device globals: allocation-free) ----------------
__device__ int   g_deg[NMAX];
__device__ float g_dis[NMAX];
__device__ __align__(16) int      g_ell[(size_t)NMAX * DEG_PAD];
__device__ __align__(16) uint32_t g_Xq [(size_t)NMAX * QROW];   // int16x2( dis * x )
__device__ __align__(16) uint32_t g_G1q[(size_t)NMAX * QROW];   // int16x2( dis * relu(A Wg1 + b) )
__device__ __align__(16) __half2  g_Ah [(size_t)NMAX * HROW];   // half2( P x )
__device__ __align__(16) __half2  g_Lh [(size_t)NMAX * HROW];   // half2( local )
__device__ __align__(16) __half2  g_Bvh[(size_t)NMAX * HROW];   // half2( P g1 )
// B fragments (fp16 hi/lo) in mma-lane layout: [img][kt<6][nt<12][lane<32]
#define FRAG_PER_IMG (6 * 12 * 32)
__device__ __align__(16) uint4 g_frag[5 * FRAG_PER_IMG];

// ---------------- packing helpers ----------------
__device__ __forceinline__ uint32_t hpack(float a, float b) {
    __half2 h = __floats2half2_rn(a, b);
    return *reinterpret_cast<uint32_t*>(&h);
}
__device__ __forceinline__ uint32_t hpack_lo(float a, float b) {
    __half2 h = __floats2half2_rn(a, b);
    float2 f = __half22float2(h);
    __half2 l = __floats2half2_rn(a - f.x, b - f.y);
    return *reinterpret_cast<uint32_t*>(&l);
}
__device__ __forceinline__ int q16(float v) {
    v = fminf(fmaxf(v, -7.99f), 7.99f);
    return __float2int_rn(v * QSCALE);
}
__device__ __forceinline__ uint32_t qpack(float a, float b) {
    return (uint32_t)(q16(a) & 0xFFFF) | ((uint32_t)q16(b) << 16);
}
// d = c + (low int16 of a)  [b=1]  or  c + (high int16 of a)  [b=0x100]
__device__ __forceinline__ int dp2a_lo(uint32_t a, int b, int c) {
    int d;
    asm("dp2a.lo.s32.s32 %0, %1, %2, %3;" : "=r"(d) : "r"(a), "r"(b), "r"(c));
    return d;
}

// ---------------- weight prep (also zeroes g_deg) ----------------
__global__ void k_prepB(const float* __restrict__ Wl, const float* __restrict__ Wg1,
                        const float* __restrict__ Wg2, const float* __restrict__ Wf,
                        int n) {
    int i = blockIdx.x * blockDim.x + threadIdx.x;
    if (i < n) g_deg[i] = 0;
    if (i >= 5 * FRAG_PER_IMG) return;
    int lane = i & 31;
    int nt   = (i >> 5) % 12;
    int kt   = ((i >> 5) / 12) % 6;
    int img  = i / FRAG_PER_IMG;

    int nn = nt * 8 + (lane >> 2);
    int k0 = kt * 16 + (lane & 3) * 2;

    const float* W;
    int koff = 0;
    if      (img == 0) W = Wl;
    else if (img == 1) W = Wg1;
    else if (img == 2) W = Wg2;
    else if (img == 3) W = Wf;
    else               { W = Wf; koff = 96; }

    float w0 = W[(size_t)(koff + k0)     * 96 + nn];
    float w1 = W[(size_t)(koff + k0 + 1) * 96 + nn];
    float w8 = W[(size_t)(koff + k0 + 8) * 96 + nn];
    float w9 = W[(size_t)(koff + k0 + 9) * 96 + nn];

    uint4 o;
    o.x = hpack(w0, w1);
    o.y = hpack(w8, w9);
    o.z = hpack_lo(w0, w1);
    o.w = hpack_lo(w8, w9);
    g_frag[i] = o;
}

// ---------------- degree / ELL build ----------------
__global__ void k_fill(const int* __restrict__ ei, int e_cnt) {
    int i = blockIdx.x * blockDim.x + threadIdx.x;
    int e0 = i * 4;
    if (e0 + 3 < e_cnt) {
        int4 s = *reinterpret_cast<const int4*>(ei + e0);
        int4 d = *reinterpret_cast<const int4*>(ei + e_cnt + e0);
        int p;
        p = atomicAdd(&g_deg[d.x], 1); if (p < DEG_PAD) g_ell[(size_t)d.x * DEG_PAD + p] = s.x;
        p = atomicAdd(&g_deg[d.y], 1); if (p < DEG_PAD) g_ell[(size_t)d.y * DEG_PAD + p] = s.y;
        p = atomicAdd(&g_deg[d.z], 1); if (p < DEG_PAD) g_ell[(size_t)d.z * DEG_PAD + p] = s.z;
        p = atomicAdd(&g_deg[d.w], 1); if (p < DEG_PAD) g_ell[(size_t)d.w * DEG_PAD + p] = s.w;
    } else {
        for (int e = e0; e < e_cnt && e < e0 + 4; e++) {
            int s = ei[e], d = ei[e_cnt + e];
            int p = atomicAdd(&g_deg[d], 1);
            if (p < DEG_PAD) g_ell[(size_t)d * DEG_PAD + p] = s;
        }
    }
}

// Xq = int16x2( dis * x ); also writes g_dis
__global__ void k_toQ(const float* __restrict__ x, int n) {
    int i = blockIdx.x * blockDim.x + threadIdx.x;
    if (i >= n * 24) return;
    int row = i / 24, q = i % 24;
    float d = rsqrtf((float)(g_deg[row] + 1));
    if (q == 0) g_dis[row] = d;
    float4 v = *reinterpret_cast<const float4*>(x + (size_t)row * FDIM + q * 4);
    uint2 o = make_uint2(qpack(d * v.x, d * v.y), qpack(d * v.z, d * v.w));
    *reinterpret_cast<uint2*>(g_Xq + (size_t)row * QROW + q * 2) = o;
}

// ---------------- aggregation: int16 gather, exact int32 accumulate, fp16 out
// Pout[i] = half2( dis[i] * QINV * ( sum_src q[src] + q[i] ) )
__global__ void __launch_bounds__(256) k_agg(const uint32_t* __restrict__ q,
                                             __half2* __restrict__ Pout, int n) {
    int warp = blockIdx.x * 8 + (threadIdx.x >> 5);
    int lane = threadIdx.x & 31;
    if (warp >= n) return;

    int cnt = g_deg[warp];
    cnt = cnt < DEG_PAD ? cnt : DEG_PAD;
    float di = g_dis[warp];
    const int* row = g_ell + (size_t)warp * DEG_PAD;
    bool act = lane < 24;     // lane owns cols 4l..4l+3 (2 uint32 = uint2)

    int a0 = 0, a1 = 0, a2 = 0, a3 = 0;
    if (act) {
        uint2 sv = *reinterpret_cast<const uint2*>(q + (size_t)warp * QROW + lane * 2);
        a0 = dp2a_lo(sv.x, 1, 0);
        a1 = dp2a_lo(sv.x, 0x100, 0);
        a2 = dp2a_lo(sv.y, 1, 0);
        a3 = dp2a_lo(sv.y, 0x100, 0);
    }

    for (int base = 0; base < cnt; base += 32) {
        int take = cnt - base; if (take > 32) take = 32;
        int s = 0;
        if (lane < take) s = row[base + lane];
        #pragma unroll 8
        for (int j = 0; j < take; j++) {
            int ss = __shfl_sync(0xffffffffu, s, j);
            if (act) {
                uint2 u = *reinterpret_cast<const uint2*>(q + (size_t)ss * QROW + lane * 2);
                a0 = dp2a_lo(u.x, 1, a0);
                a1 = dp2a_lo(u.x, 0x100, a1);
                a2 = dp2a_lo(u.y, 1, a2);
                a3 = dp2a_lo(u.y, 0x100, a3);
            }
        }
    }
    if (act) {
        float sc = di * QINV;
        uint2 o = make_uint2(hpack((float)a0 * sc, (float)a1 * sc),
                             hpack((float)a2 * sc, (float)a3 * sc));
        *reinterpret_cast<uint2*>(Pout + (size_t)warp * HROW + lane * 2) = o;
    }
}

// ---------------- mma.sync f16 GEMM (HMMA path, portable PTX) ----------------
__device__ __forceinline__ void mma16816(float acc[4], const uint32_t a[4],
                                         uint32_t b0, uint32_t b1) {
    asm volatile(
        "mma.sync.aligned.m16n8k16.row.col.f32.f16.f16.f32 "
        "{%0,%1,%2,%3}, {%4,%5,%6,%7}, {%8,%9}, {%0,%1,%2,%3};"
        : "+f"(acc[0]), "+f"(acc[1]), "+f"(acc[2]), "+f"(acc[3])
        : "r"(a[0]), "r"(a[1]), "r"(a[2]), "r"(a[3]), "r"(b0), "r"(b1));
}

// load fp16 a-frags for one kt: 4 LDG.32
__device__ __forceinline__ void load_afrag(const uint32_t* __restrict__ P,
                                           int ra, int rb, int M, int kt, int lane,
                                           uint32_t ah[4]) {
    int c0 = kt * 8 + (lane & 3);
    ah[0] = (ra < M) ? P[(size_t)ra * HROW + c0]     : 0u;
    ah[1] = (rb < M) ? P[(size_t)rb * HROW + c0]     : 0u;
    ah[2] = (ra < M) ? P[(size_t)ra * HROW + c0 + 4] : 0u;
    ah[3] = (rb < M) ? P[(size_t)rb * HROW + c0 + 4] : 0u;
}

// one K=96 chunk into acc: 2 mmas per (kt,nt)  (A fp16, B = bhi + blo)
__device__ __forceinline__ void gemm_chunk(const __half2* __restrict__ Ph,
                                           const uint4* __restrict__ F,
                                           int row0, int lane, int M,
                                           float acc[12][4]) {
    const uint32_t* P = reinterpret_cast<const uint32_t*>(Ph);
    int r  = lane >> 2;
    int ra = row0 + r, rb = row0 + r + 8;
    #pragma unroll
    for (int kt = 0; kt < 6; kt++) {
        uint32_t ah[4];
        load_afrag(P, ra, rb, M, kt, lane, ah);
        const uint4* fp = F + (size_t)kt * 12 * 32 + lane;
        #pragma unroll
        for (int nt = 0; nt < 12; nt++) {
            uint4 b = fp[nt * 32];
            mma16816(acc[nt], ah, b.x, b.y);   // a * bhi
            mma16816(acc[nt], ah, b.z, b.w);   // a * blo
        }
    }
}

// dual-output GEMM sharing fp16 input A:
//   Lh = half2(relu(A W1 + b1));  G1q = int16x2( dis * relu(A W2 + b2) )
__global__ void __launch_bounds__(256)
k_dualgemm(const __half2* __restrict__ Ph,
           const uint4* __restrict__ F1, const uint4* __restrict__ F2,
           const float* __restrict__ bias1, const float* __restrict__ bias2,
           __half2* __restrict__ Lh, uint32_t* __restrict__ G1q, int M) {
    int lane = threadIdx.x & 31, warp = threadIdx.x >> 5;
    int row0 = blockIdx.x * 128 + warp * 16;
    int r  = lane >> 2;
    int cq = (lane & 3) * 2;
    int ra = row0 + r, rb = row0 + r + 8;

    float acc1[12][4], acc2[12][4];
    #pragma unroll
    for (int nt = 0; nt < 12; nt++)
        #pragma unroll
        for (int j = 0; j < 4; j++) { acc1[nt][j] = 0.f; acc2[nt][j] = 0.f; }

    const uint32_t* P = reinterpret_cast<const uint32_t*>(Ph);
    #pragma unroll
    for (int kt = 0; kt < 6; kt++) {
        uint32_t ah[4];
        load_afrag(P, ra, rb, M, kt, lane, ah);
        const uint4* fp1 = F1 + (size_t)kt * 12 * 32 + lane;
        const uint4* fp2 = F2 + (size_t)kt * 12 * 32 + lane;
        #pragma unroll
        for (int nt = 0; nt < 12; nt++) {
            uint4 b1 = fp1[nt * 32];
            mma16816(acc1[nt], ah, b1.x, b1.y);
            mma16816(acc1[nt], ah, b1.z, b1.w);
            uint4 b2 = fp2[nt * 32];
            mma16816(acc2[nt], ah, b2.x, b2.y);
            mma16816(acc2[nt], ah, b2.z, b2.w);
        }
    }

    float da = (ra < M) ? g_dis[ra] : 0.f;
    float db = (rb < M) ? g_dis[rb] : 0.f;
    uint32_t* Lw = reinterpret_cast<uint32_t*>(Lh);
    #pragma unroll
    for (int nt = 0; nt < 12; nt++) {
        int col = nt * 8 + cq;
        int cpi = col >> 1;
        float2 bb1 = *reinterpret_cast<const float2*>(bias1 + col);
        float2 bb2 = *reinterpret_cast<const float2*>(bias2 + col);
        if (ra < M) {
            Lw [(size_t)ra * HROW + cpi] = hpack(fmaxf(acc1[nt][0] + bb1.x, 0.f),
                                                fmaxf(acc1[nt][1] + bb1.y, 0.f));
            G1q[(size_t)ra * QROW + cpi] = qpack(da * fmaxf(acc2[nt][0] + bb2.x, 0.f),
                                                 da * fmaxf(acc2[nt][1] + bb2.y, 0.f));
        }
        if (rb < M) {
            Lw [(size_t)rb * HROW + cpi] = hpack(fmaxf(acc1[nt][2] + bb1.x, 0.f),
                                                fmaxf(acc1[nt][3] + bb1.y, 0.f));
            G1q[(size_t)rb * QROW + cpi] = qpack(db * fmaxf(acc2[nt][2] + bb2.x, 0.f),
                                                 db * fmaxf(acc2[nt][3] + bb2.y, 0.f));
        }
    }
}

// fused: g2 = relu(Bv Wg2 + b_g2) in registers; out = L Wf_top + g2 Wf_bot + b_fuse
__global__ void __launch_bounds__(256)
k_fuse2(const __half2* __restrict__ Bvh, const __half2* __restrict__ Lh,
        const uint4* __restrict__ Fg2, const uint4* __restrict__ Ftop,
        const uint4* __restrict__ Fbot,
        const float* __restrict__ bias_g2, const float* __restrict__ bias_f,
        float* __restrict__ out, int M) {
    int lane = threadIdx.x & 31, warp = threadIdx.x >> 5;
    int row0 = blockIdx.x * 128 + warp * 16;
    int r  = lane >> 2;
    int cq = (lane & 3) * 2;
    int ra = row0 + r, rb = row0 + r + 8;

    // phase 1: g2 accumulators
    float g2[12][4];
    #pragma unroll
    for (int nt = 0; nt < 12; nt++)
        #pragma unroll
        for (int j = 0; j < 4; j++) g2[nt][j] = 0.f;
    gemm_chunk(Bvh, Fg2, row0, lane, M, g2);
    #pragma unroll
    for (int nt = 0; nt < 12; nt++) {
        int col = nt * 8 + cq;
        float2 bb = *reinterpret_cast<const float2*>(bias_g2 + col);
        g2[nt][0] = fmaxf(g2[nt][0] + bb.x, 0.f);
        g2[nt][1] = fmaxf(g2[nt][1] + bb.y, 0.f);
        g2[nt][2] = fmaxf(g2[nt][2] + bb.x, 0.f);
        g2[nt][3] = fmaxf(g2[nt][3] + bb.y, 0.f);
    }

    // phase 2: out = L @ Wf_top
    float acc[12][4];
    #pragma unroll
    for (int nt = 0; nt < 12; nt++)
        #pragma unroll
        for (int j = 0; j < 4; j++) acc[nt][j] = 0.f;
    gemm_chunk(Lh, Ftop, row0, lane, M, acc);

    // phase 3: out += g2 @ Wf_bot (C-frag of g2 reinterpreted as A-frags, fp16)
    #pragma unroll
    for (int kt = 0; kt < 6; kt++) {
        uint32_t ah[4] = { hpack(g2[2*kt][0],   g2[2*kt][1]),
                           hpack(g2[2*kt][2],   g2[2*kt][3]),
                           hpack(g2[2*kt+1][0], g2[2*kt+1][1]),
                           hpack(g2[2*kt+1][2], g2[2*kt+1][3]) };
        const uint4* fp = Fbot + (size_t)kt * 12 * 32 + lane;
        #pragma unroll
        for (int nt = 0; nt < 12; nt++) {
            uint4 b = fp[nt * 32];
            mma16816(acc[nt], ah, b.x, b.y);
            mma16816(acc[nt], ah, b.z, b.w);
        }
    }

    #pragma unroll
    for (int nt = 0; nt < 12; nt++) {
        int col = nt * 8 + cq;
        float2 bb = *reinterpret_cast<const float2*>(bias_f + col);
        float2 va = make_float2(acc[nt][0] + bb.x, acc[nt][1] + bb.y);
        float2 vb = make_float2(acc[nt][2] + bb.x, acc[nt][3] + bb.y);
        if (ra < M) *reinterpret_cast<float2*>(out + (size_t)ra * FDIM + col) = va;
        if (rb < M) *reinterpret_cast<float2*>(out + (size_t)rb * FDIM + col) = vb;
    }
}

// ---------------- launch ----------------
extern "C" void kernel_launch(void* const* d_in, const int* in_sizes, int n_in,
                              void* d_out, int out_size) {
    const float* x       = (const float*)d_in[0];
    const int*   ei      = (const int*)  d_in[1];
    const float* W_local = (const float*)d_in[2];
    const float* b_local = (const float*)d_in[3];
    const float* W_g1    = (const float*)d_in[4];
    const float* b_g1    = (const float*)d_in[5];
    const float* W_g2    = (const float*)d_in[6];
    const float* b_g2    = (const float*)d_in[7];
    const float* W_fuse  = (const float*)d_in[8];
    const float* b_fuse  = (const float*)d_in[9];
    float* out = (float*)d_out;

    int n = in_sizes[0] / FDIM; if (n > NMAX) n = NMAX;
    int e = in_sizes[1] / 2;    if (e > EMAX) e = EMAX;

    __half2 *pAh, *pLh, *pBvh;
    uint32_t *pXq, *pG1q;
    uint4* pF;
    cudaGetSymbolAddress((void**)&pXq,  g_Xq);
    cudaGetSymbolAddress((void**)&pG1q, g_G1q);
    cudaGetSymbolAddress((void**)&pAh,  g_Ah);
    cudaGetSymbolAddress((void**)&pLh,  g_Lh);
    cudaGetSymbolAddress((void**)&pBvh, g_Bvh);
    cudaGetSymbolAddress((void**)&pF,   g_frag);

    const int tb = 256;
    int eq = (e + 3) / 4;
    int prepThreads = (n > 5 * FRAG_PER_IMG) ? n : 5 * FRAG_PER_IMG;
    // prepB also zeroes g_deg — must precede k_fill
    k_prepB<<<(prepThreads + tb - 1) / tb, tb>>>(W_local, W_g1, W_g2, W_fuse, n);
    k_fill <<<(eq + tb - 1) / tb, tb>>>(ei, e);
    // toQ computes dis from deg (needs fill done) and quantizes dis*x
    k_toQ  <<<(n * 24 + tb - 1) / tb, tb>>>(x, n);

    int aggGrid = (n + 7) / 8;
    int gGrid   = (n + 127) / 128;

    // Ah = half(P x)   (int16 gather)
    k_agg<<<aggGrid, 256>>>(pXq, pAh, n);
    // Lh = half(relu(A Wl + b)); G1q = int16(dis * relu(A Wg1 + b))
    k_dualgemm<<<gGrid, 256>>>(pAh, pF + 0 * FRAG_PER_IMG, pF + 1 * FRAG_PER_IMG,
                               b_local, b_g1, pLh, pG1q, n);
    // Bvh = half(P g1)  (int16 gather)
    k_agg<<<aggGrid, 256>>>(pG1q, pBvh, n);
    // out = L Wf_top + relu(Bv Wg2 + b) Wf_bot + b_fuse
    k_fuse2<<<gGrid, 256>>>(pBvh, pLh,
                            pF + 2 * FRAG_PER_IMG, pF + 3 * FRAG_PER_IMG, pF + 4 * FRAG_PER_IMG,
                            b_g2, b_fuse, out, n);
}

// round 14
// speedup vs baseline: 1.0804x; 1.0804x over previous
#include <cuda_runtime.h>
#include <cuda_fp16.h>
#include <cstdint>

#define NMAX 50000
#define EMAX 800000
#define FDIM 96
#define DEG_PAD 128
#define HROW 48   // half2 per row

// ---------------- scratch (device globals: allocation-free) ----------------
__device__ int   g_deg[NMAX];
__device__ float g_dis[NMAX];
__device__ __align__(16) int     g_ell[(size_t)NMAX * DEG_PAD];
__device__ __align__(16) float   g_Xs [(size_t)NMAX * FDIM];   // dis * x (fp32)
__device__ __align__(16) float   g_G1s[(size_t)NMAX * FDIM];   // dis * relu(A Wg1 + b) (fp32)
__device__ __align__(16) __half2 g_Ah [(size_t)NMAX * HROW];   // half2( P x )
__device__ __align__(16) __half2 g_Lh [(size_t)NMAX * HROW];   // half2( local )
__device__ __align__(16) __half2 g_Bvh[(size_t)NMAX * HROW];   // half2( P g1 )
// B fragments (fp16 hi/lo) in mma-lane layout: [img][kt<6][nt<12][lane<32]
#define FRAG_PER_IMG (6 * 12 * 32)
__device__ __align__(16) uint4 g_frag[5 * FRAG_PER_IMG];

// ---------------- packing helpers ----------------
__device__ __forceinline__ uint32_t hpack(float a, float b) {
    __half2 h = __floats2half2_rn(a, b);
    return *reinterpret_cast<uint32_t*>(&h);
}
__device__ __forceinline__ uint32_t hpack_lo(float a, float b) {
    __half2 h = __floats2half2_rn(a, b);
    float2 f = __half22float2(h);
    __half2 l = __floats2half2_rn(a - f.x, b - f.y);
    return *reinterpret_cast<uint32_t*>(&l);
}
// acc += v (packed f32x2 via FFMA2, proven-portable on this harness)
__device__ __forceinline__ void facc2(unsigned long long& acc, unsigned long long v,
                                      unsigned long long one2) {
    asm("fma.rn.f32x2 %0, %1, %2, %0;" : "+l"(acc) : "l"(v), "l"(one2));
}
__device__ __forceinline__ float2 unpack2(unsigned long long v) {
    float2 r;
    asm("mov.b64 {%0, %1}, %2;" : "=f"(r.x), "=f"(r.y) : "l"(v));
    return r;
}

// ---------------- weight prep (also zeroes g_deg) ----------------
__global__ void k_prepB(const float* __restrict__ Wl, const float* __restrict__ Wg1,
                        const float* __restrict__ Wg2, const float* __restrict__ Wf,
                        int n) {
    int i = blockIdx.x * blockDim.x + threadIdx.x;
    if (i < n) g_deg[i] = 0;
    if (i >= 5 * FRAG_PER_IMG) return;
    int lane = i & 31;
    int nt   = (i >> 5) % 12;
    int kt   = ((i >> 5) / 12) % 6;
    int img  = i / FRAG_PER_IMG;

    int nn = nt * 8 + (lane >> 2);
    int k0 = kt * 16 + (lane & 3) * 2;

    const float* W;
    int koff = 0;
    if      (img == 0) W = Wl;
    else if (img == 1) W = Wg1;
    else if (img == 2) W = Wg2;
    else if (img == 3) W = Wf;
    else               { W = Wf; koff = 96; }

    float w0 = W[(size_t)(koff + k0)     * 96 + nn];
    float w1 = W[(size_t)(koff + k0 + 1) * 96 + nn];
    float w8 = W[(size_t)(koff + k0 + 8) * 96 + nn];
    float w9 = W[(size_t)(koff + k0 + 9) * 96 + nn];

    uint4 o;
    o.x = hpack(w0, w1);
    o.y = hpack(w8, w9);
    o.z = hpack_lo(w0, w1);
    o.w = hpack_lo(w8, w9);
    g_frag[i] = o;
}

// ---------------- degree / ELL build ----------------
__global__ void k_fill(const int* __restrict__ ei, int e_cnt) {
    int i = blockIdx.x * blockDim.x + threadIdx.x;
    int e0 = i * 4;
    if (e0 + 3 < e_cnt) {
        int4 s = *reinterpret_cast<const int4*>(ei + e0);
        int4 d = *reinterpret_cast<const int4*>(ei + e_cnt + e0);
        int p;
        p = atomicAdd(&g_deg[d.x], 1); if (p < DEG_PAD) g_ell[(size_t)d.x * DEG_PAD + p] = s.x;
        p = atomicAdd(&g_deg[d.y], 1); if (p < DEG_PAD) g_ell[(size_t)d.y * DEG_PAD + p] = s.y;
        p = atomicAdd(&g_deg[d.z], 1); if (p < DEG_PAD) g_ell[(size_t)d.z * DEG_PAD + p] = s.z;
        p = atomicAdd(&g_deg[d.w], 1); if (p < DEG_PAD) g_ell[(size_t)d.w * DEG_PAD + p] = s.w;
    } else {
        for (int e = e0; e < e_cnt && e < e0 + 4; e++) {
            int s = ei[e], d = ei[e_cnt + e];
            int p = atomicAdd(&g_deg[d], 1);
            if (p < DEG_PAD) g_ell[(size_t)d * DEG_PAD + p] = s;
        }
    }
}

// Xs = dis * x (fp32); also writes g_dis
__global__ void k_toF(const float* __restrict__ x, int n) {
    int i = blockIdx.x * blockDim.x + threadIdx.x;
    if (i >= n * 24) return;
    int row = i / 24, q = i % 24;
    float d = rsqrtf((float)(g_deg[row] + 1));
    if (q == 0) g_dis[row] = d;
    float4 v = *reinterpret_cast<const float4*>(x + (size_t)row * FDIM + q * 4);
    v.x *= d; v.y *= d; v.z *= d; v.w *= d;
    *reinterpret_cast<float4*>(g_Xs + (size_t)row * FDIM + q * 4) = v;
}

// ---------------- aggregation: fp32 gather, packed f32x2 accumulate, fp16 out
// Pout[i] = half2( dis[i] * ( sum_src h[src] + h[i] ) ), h prescaled fp32
__global__ void __launch_bounds__(256) k_agg(const float* __restrict__ h,
                                             __half2* __restrict__ Pout, int n) {
    int warp = blockIdx.x * 8 + (threadIdx.x >> 5);
    int lane = threadIdx.x & 31;
    if (warp >= n) return;

    int cnt = g_deg[warp];
    cnt = cnt < DEG_PAD ? cnt : DEG_PAD;
    float di = g_dis[warp];
    const int* row = g_ell + (size_t)warp * DEG_PAD;
    bool act = lane < 24;     // lane owns cols 4l..4l+3 (one ulonglong2)

    unsigned long long one2;
    asm("mov.b64 %0, {%1, %1};" : "=l"(one2) : "f"(1.0f));

    unsigned long long a01 = 0, a23 = 0;
    if (act) {
        ulonglong2 sv = *(reinterpret_cast<const ulonglong2*>(h + (size_t)warp * FDIM) + lane);
        a01 = sv.x; a23 = sv.y;
    }

    for (int base = 0; base < cnt; base += 32) {
        int take = cnt - base; if (take > 32) take = 32;
        int s = 0;
        if (lane < take) s = row[base + lane];
        #pragma unroll 8
        for (int j = 0; j < take; j++) {
            int ss = __shfl_sync(0xffffffffu, s, j);
            if (act) {
                ulonglong2 u = *(reinterpret_cast<const ulonglong2*>(h + (size_t)ss * FDIM) + lane);
                facc2(a01, u.x, one2);
                facc2(a23, u.y, one2);
            }
        }
    }
    if (act) {
        float2 f01 = unpack2(a01);
        float2 f23 = unpack2(a23);
        uint2 o = make_uint2(hpack(di * f01.x, di * f01.y),
                             hpack(di * f23.x, di * f23.y));
        *reinterpret_cast<uint2*>(Pout + (size_t)warp * HROW + lane * 2) = o;
    }
}

// ---------------- mma.sync f16 GEMM (HMMA path, portable PTX) ----------------
__device__ __forceinline__ void mma16816(float acc[4], const uint32_t a[4],
                                         uint32_t b0, uint32_t b1) {
    asm volatile(
        "mma.sync.aligned.m16n8k16.row.col.f32.f16.f16.f32 "
        "{%0,%1,%2,%3}, {%4,%5,%6,%7}, {%8,%9}, {%0,%1,%2,%3};"
        : "+f"(acc[0]), "+f"(acc[1]), "+f"(acc[2]), "+f"(acc[3])
        : "r"(a[0]), "r"(a[1]), "r"(a[2]), "r"(a[3]), "r"(b0), "r"(b1));
}

// load fp16 a-frags for one kt: 4 LDG.32
__device__ __forceinline__ void load_afrag(const uint32_t* __restrict__ P,
                                           int ra, int rb, int M, int kt, int lane,
                                           uint32_t ah[4]) {
    int c0 = kt * 8 + (lane & 3);
    ah[0] = (ra < M) ? P[(size_t)ra * HROW + c0]     : 0u;
    ah[1] = (rb < M) ? P[(size_t)rb * HROW + c0]     : 0u;
    ah[2] = (ra < M) ? P[(size_t)ra * HROW + c0 + 4] : 0u;
    ah[3] = (rb < M) ? P[(size_t)rb * HROW + c0 + 4] : 0u;
}

// one K=96 chunk into acc: 2 mmas per (kt,nt)  (A fp16, B = bhi + blo)
__device__ __forceinline__ void gemm_chunk(const __half2* __restrict__ Ph,
                                           const uint4* __restrict__ F,
                                           int row0, int lane, int M,
                                           float acc[12][4]) {
    const uint32_t* P = reinterpret_cast<const uint32_t*>(Ph);
    int r  = lane >> 2;
    int ra = row0 + r, rb = row0 + r + 8;
    #pragma unroll
    for (int kt = 0; kt < 6; kt++) {
        uint32_t ah[4];
        load_afrag(P, ra, rb, M, kt, lane, ah);
        const uint4* fp = F + (size_t)kt * 12 * 32 + lane;
        #pragma unroll
        for (int nt = 0; nt < 12; nt++) {
            uint4 b = fp[nt * 32];
            mma16816(acc[nt], ah, b.x, b.y);   // a * bhi
            mma16816(acc[nt], ah, b.z, b.w);   // a * blo
        }
    }
}

// dual-output GEMM sharing fp16 input A:
//   Lh = half2(relu(A W1 + b1));  G1s = fp32( dis * relu(A W2 + b2) )
__global__ void __launch_bounds__(256)
k_dualgemm(const __half2* __restrict__ Ph,
           const uint4* __restrict__ F1, const uint4* __restrict__ F2,
           const float* __restrict__ bias1, const float* __restrict__ bias2,
           __half2* __restrict__ Lh, float* __restrict__ G1s, int M) {
    int lane = threadIdx.x & 31, warp = threadIdx.x >> 5;
    int row0 = blockIdx.x * 128 + warp * 16;
    int r  = lane >> 2;
    int cq = (lane & 3) * 2;
    int ra = row0 + r, rb = row0 + r + 8;

    float acc1[12][4], acc2[12][4];
    #pragma unroll
    for (int nt = 0; nt < 12; nt++)
        #pragma unroll
        for (int j = 0; j < 4; j++) { acc1[nt][j] = 0.f; acc2[nt][j] = 0.f; }

    const uint32_t* P = reinterpret_cast<const uint32_t*>(Ph);
    #pragma unroll
    for (int kt = 0; kt < 6; kt++) {
        uint32_t ah[4];
        load_afrag(P, ra, rb, M, kt, lane, ah);
        const uint4* fp1 = F1 + (size_t)kt * 12 * 32 + lane;
        const uint4* fp2 = F2 + (size_t)kt * 12 * 32 + lane;
        #pragma unroll
        for (int nt = 0; nt < 12; nt++) {
            uint4 b1 = fp1[nt * 32];
            mma16816(acc1[nt], ah, b1.x, b1.y);
            mma16816(acc1[nt], ah, b1.z, b1.w);
            uint4 b2 = fp2[nt * 32];
            mma16816(acc2[nt], ah, b2.x, b2.y);
            mma16816(acc2[nt], ah, b2.z, b2.w);
        }
    }

    float da = (ra < M) ? g_dis[ra] : 0.f;
    float db = (rb < M) ? g_dis[rb] : 0.f;
    uint32_t* Lw = reinterpret_cast<uint32_t*>(Lh);
    #pragma unroll
    for (int nt = 0; nt < 12; nt++) {
        int col = nt * 8 + cq;
        int cpi = col >> 1;
        float2 bb1 = *reinterpret_cast<const float2*>(bias1 + col);
        float2 bb2 = *reinterpret_cast<const float2*>(bias2 + col);
        if (ra < M) {
            Lw[(size_t)ra * HROW + cpi] = hpack(fmaxf(acc1[nt][0] + bb1.x, 0.f),
                                               fmaxf(acc1[nt][1] + bb1.y, 0.f));
            *reinterpret_cast<float2*>(G1s + (size_t)ra * FDIM + col) =
                make_float2(da * fmaxf(acc2[nt][0] + bb2.x, 0.f),
                            da * fmaxf(acc2[nt][1] + bb2.y, 0.f));
        }
        if (rb < M) {
            Lw[(size_t)rb * HROW + cpi] = hpack(fmaxf(acc1[nt][2] + bb1.x, 0.f),
                                               fmaxf(acc1[nt][3] + bb1.y, 0.f));
            *reinterpret_cast<float2*>(G1s + (size_t)rb * FDIM + col) =
                make_float2(db * fmaxf(acc2[nt][2] + bb2.x, 0.f),
                            db * fmaxf(acc2[nt][3] + bb2.y, 0.f));
        }
    }
}

// fused: g2 = relu(Bv Wg2 + b_g2) in registers; out = L Wf_top + g2 Wf_bot + b_fuse
__global__ void __launch_bounds__(256)
k_fuse2(const __half2* __restrict__ Bvh, const __half2* __restrict__ Lh,
        const uint4* __restrict__ Fg2, const uint4* __restrict__ Ftop,
        const uint4* __restrict__ Fbot,
        const float* __restrict__ bias_g2, const float* __restrict__ bias_f,
        float* __restrict__ out, int M) {
    int lane = threadIdx.x & 31, warp = threadIdx.x >> 5;
    int row0 = blockIdx.x * 128 + warp * 16;
    int r  = lane >> 2;
    int cq = (lane & 3) * 2;
    int ra = row0 + r, rb = row0 + r + 8;

    // phase 1: g2 accumulators
    float g2[12][4];
    #pragma unroll
    for (int nt = 0; nt < 12; nt++)
        #pragma unroll
        for (int j = 0; j < 4; j++) g2[nt][j] = 0.f;
    gemm_chunk(Bvh, Fg2, row0, lane, M, g2);
    #pragma unroll
    for (int nt = 0; nt < 12; nt++) {
        int col = nt * 8 + cq;
        float2 bb = *reinterpret_cast<const float2*>(bias_g2 + col);
        g2[nt][0] = fmaxf(g2[nt][0] + bb.x, 0.f);
        g2[nt][1] = fmaxf(g2[nt][1] + bb.y, 0.f);
        g2[nt][2] = fmaxf(g2[nt][2] + bb.x, 0.f);
        g2[nt][3] = fmaxf(g2[nt][3] + bb.y, 0.f);
    }

    // phase 2: out = L @ Wf_top
    float acc[12][4];
    #pragma unroll
    for (int nt = 0; nt < 12; nt++)
        #pragma unroll
        for (int j = 0; j < 4; j++) acc[nt][j] = 0.f;
    gemm_chunk(Lh, Ftop, row0, lane, M, acc);

    // phase 3: out += g2 @ Wf_bot (C-frag of g2 reinterpreted as A-frags, fp16)
    #pragma unroll
    for (int kt = 0; kt < 6; kt++) {
        uint32_t ah[4] = { hpack(g2[2*kt][0],   g2[2*kt][1]),
                           hpack(g2[2*kt][2],   g2[2*kt][3]),
                           hpack(g2[2*kt+1][0], g2[2*kt+1][1]),
                           hpack(g2[2*kt+1][2], g2[2*kt+1][3]) };
        const uint4* fp = Fbot + (size_t)kt * 12 * 32 + lane;
        #pragma unroll
        for (int nt = 0; nt < 12; nt++) {
            uint4 b = fp[nt * 32];
            mma16816(acc[nt], ah, b.x, b.y);
            mma16816(acc[nt], ah, b.z, b.w);
        }
    }

    #pragma unroll
    for (int nt = 0; nt < 12; nt++) {
        int col = nt * 8 + cq;
        float2 bb = *reinterpret_cast<const float2*>(bias_f + col);
        float2 va = make_float2(acc[nt][0] + bb.x, acc[nt][1] + bb.y);
        float2 vb = make_float2(acc[nt][2] + bb.x, acc[nt][3] + bb.y);
        if (ra < M) *reinterpret_cast<float2*>(out + (size_t)ra * FDIM + col) = va;
        if (rb < M) *reinterpret_cast<float2*>(out + (size_t)rb * FDIM + col) = vb;
    }
}

// ---------------- launch ----------------
extern "C" void kernel_launch(void* const* d_in, const int* in_sizes, int n_in,
                              void* d_out, int out_size) {
    const float* x       = (const float*)d_in[0];
    const int*   ei      = (const int*)  d_in[1];
    const float* W_local = (const float*)d_in[2];
    const float* b_local = (const float*)d_in[3];
    const float* W_g1    = (const float*)d_in[4];
    const float* b_g1    = (const float*)d_in[5];
    const float* W_g2    = (const float*)d_in[6];
    const float* b_g2    = (const float*)d_in[7];
    const float* W_fuse  = (const float*)d_in[8];
    const float* b_fuse  = (const float*)d_in[9];
    float* out = (float*)d_out;

    int n = in_sizes[0] / FDIM; if (n > NMAX) n = NMAX;
    int e = in_sizes[1] / 2;    if (e > EMAX) e = EMAX;

    __half2 *pAh, *pLh, *pBvh;
    float *pXs, *pG1s;
    uint4* pF;
    cudaGetSymbolAddress((void**)&pXs,  g_Xs);
    cudaGetSymbolAddress((void**)&pG1s, g_G1s);
    cudaGetSymbolAddress((void**)&pAh,  g_Ah);
    cudaGetSymbolAddress((void**)&pLh,  g_Lh);
    cudaGetSymbolAddress((void**)&pBvh, g_Bvh);
    cudaGetSymbolAddress((void**)&pF,   g_frag);

    const int tb = 256;
    int eq = (e + 3) / 4;
    int prepThreads = (n > 5 * FRAG_PER_IMG) ? n : 5 * FRAG_PER_IMG;
    // prepB also zeroes g_deg — must precede k_fill
    k_prepB<<<(prepThreads + tb - 1) / tb, tb>>>(W_local, W_g1, W_g2, W_fuse, n);
    k_fill <<<(eq + tb - 1) / tb, tb>>>(ei, e);
    // toF computes dis from deg (needs fill done) and prescales x (fp32)
    k_toF  <<<(n * 24 + tb - 1) / tb, tb>>>(x, n);

    int aggGrid = (n + 7) / 8;
    int gGrid   = (n + 127) / 128;

    // Ah = half(P x)   (fp32 gather, f32x2 accumulate)
    k_agg<<<aggGrid, 256>>>(pXs, pAh, n);
    // Lh = half(relu(A Wl + b)); G1s = fp32(dis * relu(A Wg1 + b))
    k_dualgemm<<<gGrid, 256>>>(pAh, pF + 0 * FRAG_PER_IMG, pF + 1 * FRAG_PER_IMG,
                               b_local, b_g1, pLh, pG1s, n);
    // Bvh = half(P g1)
    k_agg<<<aggGrid, 256>>>(pG1s, pBvh, n);
    // out = L Wf_top + relu(Bv Wg2 + b) Wf_bot + b_fuse
    k_fuse2<<<gGrid, 256>>>(pBvh, pLh,
                            pF + 2 * FRAG_PER_IMG, pF + 3 * FRAG_PER_IMG, pF + 4 * FRAG_PER_IMG,
                            b_g2, b_fuse, out, n);
}